// round 17
// baseline (speedup 1.0000x reference)
#include <cuda_runtime.h>

// LengthRegulator — champion family, 2 tokens per block:
// single fused kernel, one graph node. Block g handles tokens j0=2g, j0+1 of
// batch b. All 192 threads compute one shared prefix sum(dur[b,0..j0)) via
// strided loads + shfl reduce (one barrier); half 1 adds dur[j0]. Each
// 96-thread half then scatters its token row with 6 predicated streaming
// stores (d in {2,4,6}; residual loop for generality). __stcs load-bearing
// (evict-normal thrashes L2 across graph replays, +4.4us measured R15).

#define BB 32
#define SS 512
#define DD 384
#define T_OUT 2048
#define DV (DD / 4)    // 96 float4 per row
#define NT 192         // 6 warps, 2 tokens
#define NW (NT / 32)

__global__ __launch_bounds__(NT)
void lr_fused_kernel(const float4* __restrict__ x4,
                     const int* __restrict__ dur,
                     float4* __restrict__ out4) {
    __shared__ int part[NW];

    const int j0   = blockIdx.x * 2;
    const int b    = blockIdx.y;
    const int t    = threadIdx.x;        // 0..191
    const int half = t / DV;             // 0 or 1 -> token j0+half
    const int c    = t % DV;             // float4 channel
    const int w    = t >> 5;
    const int lane = t & 31;
    const int j    = j0 + half;
    const int* dr  = dur + b * SS;

    // Long-latency loads first; they overlap the prefix reduce.
    const float4 v  = __ldg(&x4[((size_t)(b * SS + j)) * DV + c]);
    const int d     = __ldg(&dr[j]);
    const int dfirst = __ldg(&dr[j0]);   // for half 1's start offset

    // ── shared prefix: sum_{p<j0} dur[b,p], strided over all 192 threads ─
    int sum = 0;
    for (int p = t; p < j0; p += NT)     // <= 3 L2-hit loads per thread
        sum += __ldg(&dr[p]);
    #pragma unroll
    for (int off = 16; off > 0; off >>= 1)
        sum += __shfl_down_sync(0xFFFFFFFFu, sum, off);
    if (lane == 0) part[w] = sum;
    __syncthreads();
    int start = part[0] + part[1] + part[2] + part[3] + part[4] + part[5];
    if (half) start += dfirst;

    // ── copy: 6 predicated streaming stores (d in {2,4,6}) ──────────────
    float4* o = out4 + ((size_t)b * T_OUT + start) * DV + c;
    __stcs(&o[0 * (size_t)DV], v);
    __stcs(&o[1 * (size_t)DV], v);
    if (d > 2) {
        __stcs(&o[2 * (size_t)DV], v);
        __stcs(&o[3 * (size_t)DV], v);
    }
    if (d > 4) {
        __stcs(&o[4 * (size_t)DV], v);
        __stcs(&o[5 * (size_t)DV], v);
    }
    for (int k = 6; k < d; ++k)          // defensive; never taken here
        __stcs(&o[(size_t)k * DV], v);
}

extern "C" void kernel_launch(void* const* d_in, const int* in_sizes, int n_in,
                              void* d_out, int out_size) {
    const float4* x4  = (const float4*)d_in[0];   // x [B,S,D] f32
    const int*    dur = (const int*)d_in[1];      // durations [B,S] i32
    float4* out4 = (float4*)d_out;                // [B,T_OUT,D] f32

    lr_fused_kernel<<<dim3(SS / 2, BB), NT>>>(x4, dur, out4);
}